// round 10
// baseline (speedup 1.0000x reference)
#include <cuda_runtime.h>
#include <cuda_fp16.h>
#include <math.h>
#include <float.h>
#include <stdint.h>

#define N_PRED 8192
#define M_TGT  16384
#define KD     128
#define MT     128
#define NT     128
#define NITEMS 8192               // 64 pred-tiles * 128 chunks
#define NCTA   296                // 2 per SM, exactly one wave
#define TOPK   5
#define ROWB   272                // padded smem row bytes (136 halves)
#define NROWS  (N_PRED + M_TGT)   // 24576

// ---------------- static device scratch ----------------
__device__ __half g_pred_h[N_PRED * KD];
__device__ __half g_tgt_h[M_TGT * KD];
__device__ float  g_a2[N_PRED];
__device__ float  g_b2[M_TGT];
// writer-indexed candidates: [cta][ptslot(2)][warpN(2)][128 rows][5]
__device__ float  g_cand2[NCTA * 2 * 2 * 128 * TOPK];
__device__ float  g_part[NCTA];
__device__ unsigned g_bar;        // monotonic grid barrier counter
__device__ unsigned g_tick;       // monotonic completion ticket

// ---------------- smem layout (bytes), total 105472 ----------------
#define SA    0
#define SB0   34816
#define SB1   69632
#define B2_0  104448
#define B2_1  104960
#define SMEM_TOTAL 105472

__device__ __forceinline__ uint32_t smem_u32(const void* p) {
    uint32_t a;
    asm("{ .reg .u64 t; cvta.to.shared.u64 t, %1; cvt.u32.u64 %0, t; }"
        : "=r"(a) : "l"(p));
    return a;
}
__device__ __forceinline__ void cp16(uint32_t dst, const void* src) {
    asm volatile("cp.async.cg.shared.global [%0], [%1], 16;"
                 :: "r"(dst), "l"(src) : "memory");
}
__device__ __forceinline__ void cp4(uint32_t dst, const void* src) {
    asm volatile("cp.async.ca.shared.global [%0], [%1], 4;"
                 :: "r"(dst), "l"(src) : "memory");
}
#define CP_COMMIT() asm volatile("cp.async.commit_group;" ::: "memory")
#define CP_WAIT0()  asm volatile("cp.async.wait_group 0;" ::: "memory")

__device__ __forceinline__ void ldsm4(uint32_t a, uint32_t& r0, uint32_t& r1,
                                      uint32_t& r2, uint32_t& r3) {
    asm volatile("ldmatrix.sync.aligned.m8n8.x4.shared.b16 {%0,%1,%2,%3}, [%4];"
                 : "=r"(r0), "=r"(r1), "=r"(r2), "=r"(r3) : "r"(a));
}
__device__ __forceinline__ void mma16816_f16(uint32_t& d0, uint32_t& d1,
                                             uint32_t a0, uint32_t a1,
                                             uint32_t a2, uint32_t a3,
                                             uint32_t b0, uint32_t b1) {
    asm volatile("mma.sync.aligned.m16n8k16.row.col.f16.f16.f16.f16 "
                 "{%0,%1}, {%2,%3,%4,%5}, {%6,%7}, {%0,%1};"
                 : "+r"(d0), "+r"(d1)
                 : "r"(a0), "r"(a1), "r"(a2), "r"(a3), "r"(b0), "r"(b1));
}

#define CE(x, y) { float _lo = fminf(x, y); float _hi = fmaxf(x, y); x = _lo; y = _hi; }

// closed-form static item partition: start(cta) = cta*27 + min(cta,200)
__device__ __forceinline__ int part_start(int cta) {
    return cta * 27 + (cta < 200 ? cta : 200);
}
__device__ __forceinline__ int cta_of(int item) {
    return (item < 5600) ? (item / 28) : ((item - 200) / 27);
}

// monotonic grid-wide barrier (no reset needed across graph replays)
__device__ __forceinline__ void grid_sync() {
    __syncthreads();
    if (threadIdx.x == 0) {
        __threadfence();
        unsigned a = atomicAdd(&g_bar, 1u) + 1u;
        unsigned target = ((a + NCTA - 1u) / NCTA) * NCTA;
        while (*(volatile unsigned*)&g_bar < target) { }
        __threadfence();
    }
    __syncthreads();
}

extern __shared__ char smem[];

__device__ __forceinline__ void flush_t5(float (&t5)[4][TOPK], int cta, int slot,
                                         int warpM, int warpN, int lane) {
    #pragma unroll
    for (int r = 0; r < 4; r++) {
        #pragma unroll
        for (int off = 1; off <= 2; off <<= 1) {
            float b[TOPK], m[TOPK];
            #pragma unroll
            for (int s = 0; s < TOPK; s++)
                b[s] = __shfl_xor_sync(0xffffffffu, t5[r][s], off);
            #pragma unroll
            for (int s = 0; s < TOPK; s++)
                m[s] = fminf(t5[r][s], b[TOPK - 1 - s]);
            CE(m[0], m[1]); CE(m[1], m[2]); CE(m[2], m[3]); CE(m[3], m[4]);
            CE(m[0], m[1]); CE(m[1], m[2]); CE(m[2], m[3]);
            CE(m[0], m[1]); CE(m[1], m[2]);
            CE(m[0], m[1]);
            #pragma unroll
            for (int s = 0; s < TOPK; s++) t5[r][s] = m[s];
        }
    }
    if ((lane & 3) == 0) {
        #pragma unroll
        for (int mf = 0; mf < 2; mf++)
            #pragma unroll
            for (int h = 0; h < 2; h++) {
                int lrow = warpM * 32 + mf * 16 + (lane >> 2) + 8 * h;
                size_t base =
                    ((((size_t)cta * 2 + slot) * 2 + warpN) * 128 + lrow) * TOPK;
                #pragma unroll
                for (int s = 0; s < TOPK; s++)
                    g_cand2[base + s] = t5[mf * 2 + h][s];
            }
    }
}

__global__ __launch_bounds__(256, 2) void fused_main(
        const float* __restrict__ pred, const float* __restrict__ tgt,
        float* __restrict__ out) {
    const int tid   = threadIdx.x;
    const int wid   = tid >> 5;
    const int lane  = tid & 31;
    const int warpM = wid >> 1;
    const int warpN = wid & 1;
    const int cta   = blockIdx.x;
    const uint32_t sbase = smem_u32(smem);

    // ================= phase 0: convert + norms =================
    {
        // rows [cs, ce): 24576 = 296*83 + 8
        const int cs = cta * 83 + min(cta, 8);
        const int ce = cs + 83 + (cta < 8 ? 1 : 0);
        const int cnt = ce - cs;
        const int wrows = (cnt + 7) >> 3;                 // rows per warp
        const int ws = cs + wid * wrows;
        const int we = min(ws + wrows, ce);
        for (int j0 = ws; j0 < we; j0 += 4) {
            const int nb = min(4, we - j0);
            float4 v[4];
            #pragma unroll
            for (int b = 0; b < 4; b++) {
                if (b < nb) {
                    int r = j0 + b;
                    const float* src = (r < M_TGT)
                        ? (tgt + (size_t)r * KD)
                        : (pred + (size_t)(r - M_TGT) * KD);
                    v[b] = ((const float4*)src)[lane];
                }
            }
            #pragma unroll
            for (int b = 0; b < 4; b++) {
                if (b < nb) {
                    int r = j0 + b;
                    float s = v[b].x * v[b].x + v[b].y * v[b].y +
                              v[b].z * v[b].z + v[b].w * v[b].w;
                    #pragma unroll
                    for (int off = 16; off; off >>= 1)
                        s += __shfl_xor_sync(0xffffffffu, s, off);
                    __half2 h0 = __floats2half2_rn(v[b].x, v[b].y);
                    __half2 h1 = __floats2half2_rn(v[b].z, v[b].w);
                    uint2 u;
                    u.x = *reinterpret_cast<unsigned*>(&h0);
                    u.y = *reinterpret_cast<unsigned*>(&h1);
                    __half* dst = (r < M_TGT)
                        ? (g_tgt_h + (size_t)r * KD)
                        : (g_pred_h + (size_t)(r - M_TGT) * KD);
                    *(uint2*)(dst + lane * 4) = u;
                    if (lane == 0) {
                        if (r < M_TGT) g_b2[r] = s;
                        else           g_a2[r - M_TGT] = s;
                    }
                }
            }
        }
    }
    grid_sync();

    // ================= phase 1: balanced HMMA + fused top-5 =================
    const int start = part_start(cta);
    const int end   = part_start(cta + 1);

    const uint32_t rowA_off =
        (uint32_t)(warpM * 32 + ((lane >> 3) & 1) * 8 + (lane & 7)) * ROWB +
        (uint32_t)(lane >> 4) * 16;
    const uint32_t rowB_off =
        (uint32_t)(warpN * 64 + ((lane >> 4) & 1) * 8 + (lane & 7)) * ROWB +
        (uint32_t)((lane >> 3) & 1) * 16;

    float t5[4][TOPK];
    #pragma unroll
    for (int r = 0; r < 4; r++)
        #pragma unroll
        for (int s = 0; s < TOPK; s++) t5[r][s] = FLT_MAX;

    // prime B for first item
    {
        const int tb = (start & 127) * NT;
        const char* gB = (const char*)g_tgt_h + (size_t)tb * 256;
        #pragma unroll
        for (int i = 0; i < 8; i++) {
            int cix = tid + i * 256;
            int r = cix >> 4, c = cix & 15;
            cp16(sbase + SB0 + r * ROWB + c * 16, gB + (size_t)r * 256 + c * 16);
        }
        if (tid < NT) cp4(sbase + B2_0 + tid * 4, g_b2 + tb + tid);
        CP_COMMIT();
    }

    int cur_pt = -1, slotidx = -1;

    for (int it = start; it < end; it++) {
        const int pt = it >> 7;
        const int p  = (it - start) & 1;
        const uint32_t sb_cur = sbase + (p ? SB1 : SB0);
        const uint32_t b2_cur = sbase + (p ? B2_1 : B2_0);

        if (pt != cur_pt) {
            if (cur_pt >= 0) {
                flush_t5(t5, cta, slotidx, warpM, warpN, lane);
                #pragma unroll
                for (int r = 0; r < 4; r++)
                    #pragma unroll
                    for (int s = 0; s < TOPK; s++) t5[r][s] = FLT_MAX;
            }
            cur_pt = pt;
            slotidx++;
            const char* gA = (const char*)g_pred_h + (size_t)pt * MT * 256;
            #pragma unroll
            for (int i = 0; i < 8; i++) {
                int cix = tid + i * 256;
                int r = cix >> 4, c = cix & 15;
                cp16(sbase + SA + r * ROWB + c * 16, gA + (size_t)r * 256 + c * 16);
            }
            CP_COMMIT();
            CP_WAIT0();
            __syncthreads();
        }

        // prefetch next B tile
        if (it + 1 < end) {
            const int tbn = ((it + 1) & 127) * NT;
            const uint32_t sb_nxt = sbase + (p ? SB0 : SB1);
            const uint32_t b2_nxt = sbase + (p ? B2_0 : B2_1);
            const char* gB = (const char*)g_tgt_h + (size_t)tbn * 256;
            #pragma unroll
            for (int i = 0; i < 8; i++) {
                int cix = tid + i * 256;
                int r = cix >> 4, c = cix & 15;
                cp16(sb_nxt + r * ROWB + c * 16, gB + (size_t)r * 256 + c * 16);
            }
            if (tid < NT) cp4(b2_nxt + tid * 4, g_b2 + tbn + tid);
            CP_COMMIT();
        }

        // ---- C(32x64, f16 acc) = A_warp(32x128) . B_warp^T ----
        uint32_t acc[2][8][2];
        #pragma unroll
        for (int mf = 0; mf < 2; mf++)
            #pragma unroll
            for (int nf = 0; nf < 8; nf++) {
                acc[mf][nf][0] = 0u;
                acc[mf][nf][1] = 0u;
            }

        #pragma unroll
        for (int ks = 0; ks < 8; ks++) {
            uint32_t a[2][4];
            #pragma unroll
            for (int mf = 0; mf < 2; mf++)
                ldsm4(sbase + SA + rowA_off + mf * (16 * ROWB) + ks * 32,
                      a[mf][0], a[mf][1], a[mf][2], a[mf][3]);
            #pragma unroll
            for (int j = 0; j < 4; j++) {
                uint32_t b0, b1, b2, b3;
                ldsm4(sb_cur + rowB_off + j * (16 * ROWB) + ks * 32, b0, b1, b2, b3);
                #pragma unroll
                for (int mf = 0; mf < 2; mf++) {
                    mma16816_f16(acc[mf][2 * j + 0][0], acc[mf][2 * j + 0][1],
                                 a[mf][0], a[mf][1], a[mf][2], a[mf][3], b0, b1);
                    mma16816_f16(acc[mf][2 * j + 1][0], acc[mf][2 * j + 1][1],
                                 a[mf][0], a[mf][1], a[mf][2], a[mf][3], b2, b3);
                }
            }
        }

        // ---- epilogue: fp32 keys + top-5 insert ----
        #pragma unroll
        for (int nf = 0; nf < 8; nf++) {
            float bb0 = *(const float*)(smem + (b2_cur - sbase) +
                         (warpN * 64 + nf * 8 + 2 * (lane & 3) + 0) * 4);
            float bb1 = *(const float*)(smem + (b2_cur - sbase) +
                         (warpN * 64 + nf * 8 + 2 * (lane & 3) + 1) * 4);
            #pragma unroll
            for (int mf = 0; mf < 2; mf++)
                #pragma unroll
                for (int h = 0; h < 2; h++) {
                    const int ri = mf * 2 + h;
                    float2 f = __half22float2(
                        *reinterpret_cast<__half2*>(&acc[mf][nf][h]));
                    float k0 = fmaf(-2.0f, f.x, bb0);
                    float k1 = fmaf(-2.0f, f.y, bb1);
                    if (k0 < t5[ri][4]) {
                        t5[ri][4] = k0;
                        CE(t5[ri][3], t5[ri][4]); CE(t5[ri][2], t5[ri][3]);
                        CE(t5[ri][1], t5[ri][2]); CE(t5[ri][0], t5[ri][1]);
                    }
                    if (k1 < t5[ri][4]) {
                        t5[ri][4] = k1;
                        CE(t5[ri][3], t5[ri][4]); CE(t5[ri][2], t5[ri][3]);
                        CE(t5[ri][1], t5[ri][2]); CE(t5[ri][0], t5[ri][1]);
                    }
                }
        }

        CP_WAIT0();
        __syncthreads();
    }

    flush_t5(t5, cta, slotidx, warpM, warpN, lane);
    grid_sync();

    // ================= phase 2: merge + hinge + reduce =================
    {
        __shared__ float ws2[8];
        // rows: 8192 = 296*27 + 200
        const int rs = cta * 27 + min(cta, 200);
        const int rcnt = 27 + (cta < 200 ? 1 : 0);
        float sum = 0.0f;
        if (tid < rcnt) {
            const int r  = rs + tid;
            const int pt = r >> 7;
            const int lr = r & 127;
            const int w0 = cta_of(pt << 7);
            const int w1 = cta_of((pt << 7) + 127);
            float m5[TOPK];
            #pragma unroll
            for (int s = 0; s < TOPK; s++) m5[s] = FLT_MAX;
            for (int w = w0; w <= w1; w++) {
                int slot = ((part_start(w) >> 7) == pt) ? 0 : 1;
                #pragma unroll
                for (int wn = 0; wn < 2; wn++) {
                    size_t base =
                        ((((size_t)w * 2 + slot) * 2 + wn) * 128 + lr) * TOPK;
                    #pragma unroll
                    for (int s = 0; s < TOPK; s++) {
                        float key = g_cand2[base + s];
                        if (key < m5[4]) {
                            m5[4] = key;
                            CE(m5[3], m5[4]); CE(m5[2], m5[3]);
                            CE(m5[1], m5[2]); CE(m5[0], m5[1]);
                        }
                    }
                }
            }
            float a2 = g_a2[r];
            #pragma unroll
            for (int s = 0; s < TOPK; s++) {
                float d2 = fmaxf(a2 + m5[s], 0.0f);
                sum += fmaxf(sqrtf(d2) - 1.0f, 0.0f);
            }
        }
        #pragma unroll
        for (int off = 16; off; off >>= 1)
            sum += __shfl_xor_sync(0xffffffffu, sum, off);
        if (lane == 0) ws2[wid] = sum;
        __syncthreads();
        if (tid == 0) {
            float t = 0.0f;
            #pragma unroll
            for (int w = 0; w < 8; w++) t += ws2[w];
            g_part[cta] = t;
            __threadfence();
            unsigned v = atomicAdd(&g_tick, 1u) + 1u;
            if ((v % NCTA) == 0) {           // last CTA of this launch
                __threadfence();
                float tot = 0.0f;
                for (int b = 0; b < NCTA; b++) tot += g_part[b];  // fixed order
                out[0] = tot * (1.0f / ((float)N_PRED * (float)TOPK));
            }
        }
    }
}

extern "C" void kernel_launch(void* const* d_in, const int* in_sizes, int n_in,
                              void* d_out, int out_size) {
    const float* pred = (const float*)d_in[0];
    const float* tgt  = (const float*)d_in[1];

    cudaFuncSetAttribute(fused_main, cudaFuncAttributeMaxDynamicSharedMemorySize,
                         SMEM_TOTAL);
    fused_main<<<NCTA, 256, SMEM_TOTAL>>>(pred, tgt, (float*)d_out);
}

// round 11
// speedup vs baseline: 1.3884x; 1.3884x over previous
#include <cuda_runtime.h>
#include <cuda_fp16.h>
#include <math.h>
#include <float.h>
#include <stdint.h>

#define N_PRED 8192
#define M_TGT  16384
#define KD     128
#define MT     128
#define NT     128
#define NITEMS 8192               // 64 pred-tiles * 128 chunks
#define NCTA   296                // 2 per SM
#define TOPK   5
#define ROWB   272                // padded smem row bytes (136 halves)

// ---------------- static device scratch ----------------
__device__ __half g_pred_h[N_PRED * KD];
__device__ __half g_tgt_h[M_TGT * KD];
__device__ float  g_a2[N_PRED];
__device__ __half g_b2h[M_TGT];
// writer-indexed candidates: [cta][ptslot(2)][warpN(2)][128 rows][5]
__device__ float  g_cand2[NCTA * 2 * 2 * 128 * TOPK];
__device__ float  g_partials[32];
__device__ int    g_ticket;

// ---------------- smem layout (bytes), total 104960 ----------------
#define SA    0
#define SB0   34816
#define SB1   69632
#define B2H0  104448
#define B2H1  104704
#define SMEM_TOTAL 104960

__device__ __forceinline__ uint32_t smem_u32(const void* p) {
    uint32_t a;
    asm("{ .reg .u64 t; cvta.to.shared.u64 t, %1; cvt.u32.u64 %0, t; }"
        : "=r"(a) : "l"(p));
    return a;
}
__device__ __forceinline__ void cp16(uint32_t dst, const void* src) {
    asm volatile("cp.async.cg.shared.global [%0], [%1], 16;"
                 :: "r"(dst), "l"(src) : "memory");
}
__device__ __forceinline__ void cp4(uint32_t dst, const void* src) {
    asm volatile("cp.async.ca.shared.global [%0], [%1], 4;"
                 :: "r"(dst), "l"(src) : "memory");
}
#define CP_COMMIT() asm volatile("cp.async.commit_group;" ::: "memory")
#define CP_WAIT0()  asm volatile("cp.async.wait_group 0;" ::: "memory")

__device__ __forceinline__ void ldsm4(uint32_t a, uint32_t& r0, uint32_t& r1,
                                      uint32_t& r2, uint32_t& r3) {
    asm volatile("ldmatrix.sync.aligned.m8n8.x4.shared.b16 {%0,%1,%2,%3}, [%4];"
                 : "=r"(r0), "=r"(r1), "=r"(r2), "=r"(r3) : "r"(a));
}
__device__ __forceinline__ void mma16816_f16(uint32_t& d0, uint32_t& d1,
                                             uint32_t a0, uint32_t a1,
                                             uint32_t a2, uint32_t a3,
                                             uint32_t b0, uint32_t b1) {
    asm volatile("mma.sync.aligned.m16n8k16.row.col.f16.f16.f16.f16 "
                 "{%0,%1}, {%2,%3,%4,%5}, {%6,%7}, {%0,%1};"
                 : "+r"(d0), "+r"(d1)
                 : "r"(a0), "r"(a1), "r"(a2), "r"(a3), "r"(b0), "r"(b1));
}

#define CE(x, y) { float _lo = fminf(x, y); float _hi = fmaxf(x, y); x = _lo; y = _hi; }
#define INS(t, v) \
    if ((v) < (t)[4]) { \
        (t)[4] = (v); \
        CE((t)[3], (t)[4]); CE((t)[2], (t)[3]); \
        CE((t)[1], (t)[2]); CE((t)[0], (t)[1]); \
    }

// closed-form static item partition: start(cta) = cta*27 + min(cta,200)
__host__ __device__ __forceinline__ int part_start(int cta) {
    return cta * 27 + (cta < 200 ? cta : 200);
}
__device__ __forceinline__ int cta_of(int item) {
    return (item < 5600) ? (item / 28) : ((item - 200) / 27);
}

// ---------------- prep: fp32 -> fp16 + norms ----------------
__global__ void prep_kernel(const float* __restrict__ pred,
                            const float* __restrict__ tgt) {
    if (blockIdx.x == 0 && threadIdx.x == 0) g_ticket = 0;
    int row  = blockIdx.x * 8 + (threadIdx.x >> 5);
    int lane = threadIdx.x & 31;
    if (row >= N_PRED + M_TGT) return;
    const float* src = (row < M_TGT) ? (tgt + (size_t)row * KD)
                                     : (pred + (size_t)(row - M_TGT) * KD);
    float4 v = ((const float4*)src)[lane];
    float s = v.x * v.x + v.y * v.y + v.z * v.z + v.w * v.w;
    #pragma unroll
    for (int off = 16; off; off >>= 1)
        s += __shfl_xor_sync(0xffffffffu, s, off);
    __half2 h0 = __floats2half2_rn(v.x, v.y);
    __half2 h1 = __floats2half2_rn(v.z, v.w);
    uint2 u;
    u.x = *reinterpret_cast<unsigned*>(&h0);
    u.y = *reinterpret_cast<unsigned*>(&h1);
    __half* dst = (row < M_TGT) ? (g_tgt_h + (size_t)row * KD)
                                : (g_pred_h + (size_t)(row - M_TGT) * KD);
    *(uint2*)(dst + lane * 4) = u;
    if (lane == 0) {
        if (row < M_TGT) g_b2h[row] = __float2half_rn(s);
        else             g_a2[row - M_TGT] = s;
    }
}

// ---------------- main: balanced HMMA + half2 stream-min top-5 ----------------
extern __shared__ char smem[];

__device__ __forceinline__ void flush_sm5(__half2 (&sm5)[4][8], int cta, int slot,
                                          int warpM, int warpN, int lane) {
    float t5[4][TOPK];
    #pragma unroll
    for (int r = 0; r < 4; r++)
        #pragma unroll
        for (int s = 0; s < TOPK; s++) t5[r][s] = FLT_MAX;
    // expand 16 class-mins per row into sorted top-5
    #pragma unroll
    for (int r = 0; r < 4; r++)
        #pragma unroll
        for (int nf = 0; nf < 8; nf++) {
            float2 f = __half22float2(sm5[r][nf]);
            INS(t5[r], f.x);
            INS(t5[r], f.y);
        }
    // quad merge: lanes 4g..4g+3 share the same rows
    #pragma unroll
    for (int r = 0; r < 4; r++) {
        #pragma unroll
        for (int off = 1; off <= 2; off <<= 1) {
            float b[TOPK], m[TOPK];
            #pragma unroll
            for (int s = 0; s < TOPK; s++)
                b[s] = __shfl_xor_sync(0xffffffffu, t5[r][s], off);
            #pragma unroll
            for (int s = 0; s < TOPK; s++)
                m[s] = fminf(t5[r][s], b[TOPK - 1 - s]);
            CE(m[0], m[1]); CE(m[1], m[2]); CE(m[2], m[3]); CE(m[3], m[4]);
            CE(m[0], m[1]); CE(m[1], m[2]); CE(m[2], m[3]);
            CE(m[0], m[1]); CE(m[1], m[2]);
            CE(m[0], m[1]);
            #pragma unroll
            for (int s = 0; s < TOPK; s++) t5[r][s] = m[s];
        }
    }
    if ((lane & 3) == 0) {
        #pragma unroll
        for (int mf = 0; mf < 2; mf++)
            #pragma unroll
            for (int h = 0; h < 2; h++) {
                int lrow = warpM * 32 + mf * 16 + (lane >> 2) + 8 * h;
                size_t base =
                    ((((size_t)cta * 2 + slot) * 2 + warpN) * 128 + lrow) * TOPK;
                #pragma unroll
                for (int s = 0; s < TOPK; s++)
                    g_cand2[base + s] = t5[mf * 2 + h][s];
            }
    }
}

__global__ __launch_bounds__(256, 2) void mma_main() {
    const int tid   = threadIdx.x;
    const int wid   = tid >> 5;
    const int lane  = tid & 31;
    const int warpM = wid >> 1;
    const int warpN = wid & 1;
    const int cta   = blockIdx.x;
    const uint32_t sbase = smem_u32(smem);

    const int start = part_start(cta);
    const int end   = part_start(cta + 1);

    const uint32_t rowA_off =
        (uint32_t)(warpM * 32 + ((lane >> 3) & 1) * 8 + (lane & 7)) * ROWB +
        (uint32_t)(lane >> 4) * 16;
    const uint32_t rowB_off =
        (uint32_t)(warpN * 64 + ((lane >> 4) & 1) * 8 + (lane & 7)) * ROWB +
        (uint32_t)((lane >> 3) & 1) * 16;

    const __half2 HINF2 = __half2half2(__ushort_as_half((unsigned short)0x7C00));
    const __half2 NEG2  = __float2half2_rn(-2.0f);

    __half2 sm5[4][8];
    #pragma unroll
    for (int r = 0; r < 4; r++)
        #pragma unroll
        for (int nf = 0; nf < 8; nf++) sm5[r][nf] = HINF2;

    // prime B for first item
    {
        const int tb = (start & 127) * NT;
        const char* gB = (const char*)g_tgt_h + (size_t)tb * 256;
        #pragma unroll
        for (int i = 0; i < 8; i++) {
            int cix = tid + i * 256;
            int r = cix >> 4, c = cix & 15;
            cp16(sbase + SB0 + r * ROWB + c * 16, gB + (size_t)r * 256 + c * 16);
        }
        if (tid < 64) cp4(sbase + B2H0 + tid * 4, g_b2h + tb + tid * 2);
        CP_COMMIT();
    }

    int cur_pt = -1, slotidx = -1;

    for (int it = start; it < end; it++) {
        const int pt = it >> 7;
        const int p  = (it - start) & 1;
        const uint32_t sb_cur = sbase + (p ? SB1 : SB0);
        const uint32_t b2_cur = sbase + (p ? B2H1 : B2H0);

        if (pt != cur_pt) {
            if (cur_pt >= 0) {
                flush_sm5(sm5, cta, slotidx, warpM, warpN, lane);
                #pragma unroll
                for (int r = 0; r < 4; r++)
                    #pragma unroll
                    for (int nf = 0; nf < 8; nf++) sm5[r][nf] = HINF2;
            }
            cur_pt = pt;
            slotidx++;
            const char* gA = (const char*)g_pred_h + (size_t)pt * MT * 256;
            #pragma unroll
            for (int i = 0; i < 8; i++) {
                int cix = tid + i * 256;
                int r = cix >> 4, c = cix & 15;
                cp16(sbase + SA + r * ROWB + c * 16, gA + (size_t)r * 256 + c * 16);
            }
            CP_COMMIT();
            CP_WAIT0();
            __syncthreads();
        }

        // prefetch next B tile
        if (it + 1 < end) {
            const int tbn = ((it + 1) & 127) * NT;
            const uint32_t sb_nxt = sbase + (p ? SB0 : SB1);
            const uint32_t b2_nxt = sbase + (p ? B2H0 : B2H1);
            const char* gB = (const char*)g_tgt_h + (size_t)tbn * 256;
            #pragma unroll
            for (int i = 0; i < 8; i++) {
                int cix = tid + i * 256;
                int r = cix >> 4, c = cix & 15;
                cp16(sb_nxt + r * ROWB + c * 16, gB + (size_t)r * 256 + c * 16);
            }
            if (tid < 64) cp4(b2_nxt + tid * 4, g_b2h + tbn + tid * 2);
            CP_COMMIT();
        }

        // ---- C(32x64, f16 acc) = A_warp(32x128) . B_warp^T ----
        uint32_t acc[2][8][2];
        #pragma unroll
        for (int mf = 0; mf < 2; mf++)
            #pragma unroll
            for (int nf = 0; nf < 8; nf++) {
                acc[mf][nf][0] = 0u;
                acc[mf][nf][1] = 0u;
            }

        #pragma unroll
        for (int ks = 0; ks < 8; ks++) {
            uint32_t a[2][4];
            #pragma unroll
            for (int mf = 0; mf < 2; mf++)
                ldsm4(sbase + SA + rowA_off + mf * (16 * ROWB) + ks * 32,
                      a[mf][0], a[mf][1], a[mf][2], a[mf][3]);
            #pragma unroll
            for (int j = 0; j < 4; j++) {
                uint32_t b0, b1, b2, b3;
                ldsm4(sb_cur + rowB_off + j * (16 * ROWB) + ks * 32, b0, b1, b2, b3);
                #pragma unroll
                for (int mf = 0; mf < 2; mf++) {
                    mma16816_f16(acc[mf][2 * j + 0][0], acc[mf][2 * j + 0][1],
                                 a[mf][0], a[mf][1], a[mf][2], a[mf][3], b0, b1);
                    mma16816_f16(acc[mf][2 * j + 1][0], acc[mf][2 * j + 1][1],
                                 a[mf][0], a[mf][1], a[mf][2], a[mf][3], b2, b3);
                }
            }
        }

        // ---- epilogue: half2 keys + unconditional stream-min ----
        #pragma unroll
        for (int nf = 0; nf < 8; nf++) {
            uint32_t b2r;
            asm volatile("ld.shared.b32 %0, [%1];" : "=r"(b2r)
                : "r"(b2_cur + (uint32_t)(warpN * 128 + nf * 16 + 4 * (lane & 3))));
            __half2 b2h2 = *reinterpret_cast<__half2*>(&b2r);
            #pragma unroll
            for (int mf = 0; mf < 2; mf++)
                #pragma unroll
                for (int h = 0; h < 2; h++) {
                    __half2 a = *reinterpret_cast<__half2*>(&acc[mf][nf][h]);
                    __half2 key = __hfma2(NEG2, a, b2h2);
                    sm5[mf * 2 + h][nf] = __hmin2(sm5[mf * 2 + h][nf], key);
                }
        }

        CP_WAIT0();
        __syncthreads();
    }

    flush_sm5(sm5, cta, slotidx, warpM, warpN, lane);
}

// ---------------- merge writer-indexed candidates -> final ----------------
__global__ void merge_kernel(float* __restrict__ out) {
    __shared__ float ws[8];
    __shared__ int is_last;
    int r  = blockIdx.x * 256 + threadIdx.x;
    int pt = r >> 7;
    int lr = r & 127;
    int w0 = cta_of(pt << 7);
    int w1 = cta_of((pt << 7) + 127);

    float t5[TOPK];
    #pragma unroll
    for (int s = 0; s < TOPK; s++) t5[s] = FLT_MAX;

    for (int w = w0; w <= w1; w++) {
        int slot = ((part_start(w) >> 7) == pt) ? 0 : 1;
        #pragma unroll
        for (int wn = 0; wn < 2; wn++) {
            size_t base = ((((size_t)w * 2 + slot) * 2 + wn) * 128 + lr) * TOPK;
            #pragma unroll
            for (int s = 0; s < TOPK; s++) {
                float key = g_cand2[base + s];
                INS(t5, key);
            }
        }
    }

    float a2 = g_a2[r];
    float sum = 0.0f;
    #pragma unroll
    for (int s = 0; s < TOPK; s++) {
        float d2 = fmaxf(a2 + t5[s], 0.0f);
        sum += fmaxf(sqrtf(d2) - 1.0f, 0.0f);
    }
    #pragma unroll
    for (int off = 16; off; off >>= 1)
        sum += __shfl_xor_sync(0xffffffffu, sum, off);
    if ((threadIdx.x & 31) == 0) ws[threadIdx.x >> 5] = sum;
    __syncthreads();
    if (threadIdx.x == 0) {
        float t = 0.0f;
        #pragma unroll
        for (int w = 0; w < 8; w++) t += ws[w];
        g_partials[blockIdx.x] = t;
        __threadfence();
        int v = atomicAdd(&g_ticket, 1);
        is_last = (v == 31) ? 1 : 0;
    }
    __syncthreads();
    if (is_last && threadIdx.x == 0) {
        __threadfence();
        float t = 0.0f;
        #pragma unroll
        for (int b = 0; b < 32; b++) t += g_partials[b];   // fixed order
        out[0] = t * (1.0f / ((float)N_PRED * (float)TOPK));
    }
}

extern "C" void kernel_launch(void* const* d_in, const int* in_sizes, int n_in,
                              void* d_out, int out_size) {
    const float* pred = (const float*)d_in[0];
    const float* tgt  = (const float*)d_in[1];

    prep_kernel<<<(N_PRED + M_TGT + 7) / 8, 256>>>(pred, tgt);

    cudaFuncSetAttribute(mma_main, cudaFuncAttributeMaxDynamicSharedMemorySize,
                         SMEM_TOTAL);
    mma_main<<<NCTA, 256, SMEM_TOTAL>>>();

    merge_kernel<<<N_PRED / 256, 256>>>((float*)d_out);
}